// round 5
// baseline (speedup 1.0000x reference)
#include <cuda_runtime.h>
#include <cstdint>
#include <cstddef>

// ---------------------------------------------------------------------------
// Problem dims (fixed)
// ---------------------------------------------------------------------------
#define BATCH   256
#define SEQ     256
#define NEMBD   256
#define NHEADS  8
#define HEADSZ  32
#define M_TOT   (BATCH * SEQ)          // 65536 rows
#define FFDIM   (4 * NEMBD)            // 1024

typedef unsigned long long u64;

// ---------------------------------------------------------------------------
// Scratch (no cudaMalloc allowed -> __device__ globals)
// ---------------------------------------------------------------------------
__device__ float g_h   [M_TOT * NEMBD];     // LN output (reused for LN1 and LN2)
__device__ float g_qkv [M_TOT * 3 * NEMBD]; // fused qkv [row][768]
__device__ float g_attn[M_TOT * NEMBD];     // attention output, [b,t, h*32+f]
__device__ float g_x1  [M_TOT * NEMBD];     // x + sa
__device__ float g_ffh [M_TOT * FFDIM];     // relu(h2@W1+b1)
__device__ float g_wqkv[NEMBD * 3 * NEMBD]; // concat(Wq|Wk|Wv) [256][768]

// ---------------------------------------------------------------------------
// Helpers
// ---------------------------------------------------------------------------
__device__ __forceinline__ uint32_t f2tf(float f) {
    uint32_t u;
    asm("cvt.rna.tf32.f32 %0, %1;" : "=r"(u) : "f"(f));
    return u;
}

__device__ __forceinline__ void mma_tf32(float acc[4], const uint32_t a[4], const uint32_t b[2]) {
    asm volatile(
        "mma.sync.aligned.m16n8k8.row.col.f32.tf32.tf32.f32 "
        "{%0,%1,%2,%3}, {%4,%5,%6,%7}, {%8,%9}, {%0,%1,%2,%3};"
        : "+f"(acc[0]), "+f"(acc[1]), "+f"(acc[2]), "+f"(acc[3])
        : "r"(a[0]), "r"(a[1]), "r"(a[2]), "r"(a[3]), "r"(b[0]), "r"(b[1]));
}

// Blackwell packed fp32 math (2x FFMA rate)
__device__ __forceinline__ u64 ffma2(u64 a, u64 b, u64 c) {
    u64 d;
    asm("fma.rn.f32x2 %0, %1, %2, %3;" : "=l"(d) : "l"(a), "l"(b), "l"(c));
    return d;
}
__device__ __forceinline__ u64 fmul2(u64 a, u64 b) {
    u64 d;
    asm("mul.rn.f32x2 %0, %1, %2;" : "=l"(d) : "l"(a), "l"(b));
    return d;
}
__device__ __forceinline__ u64 pack2(float x, float y) {
    u64 d;
    asm("mov.b64 %0, {%1, %2};" : "=l"(d) : "f"(x), "f"(y));
    return d;
}
__device__ __forceinline__ float2 unpack2(u64 v) {
    float2 f;
    asm("mov.b64 {%0, %1}, %2;" : "=f"(f.x), "=f"(f.y) : "l"(v));
    return f;
}

// ---------------------------------------------------------------------------
// Kernel 0: concat Wq|Wk|Wv into [256][768]
// ---------------------------------------------------------------------------
__global__ void concat_w_kernel(const float* __restrict__ Wq,
                                const float* __restrict__ Wk,
                                const float* __restrict__ Wv,
                                float* __restrict__ W) {
    int i = blockIdx.x * 256 + threadIdx.x;      // 0 .. 256*768-1
    int d = i / 768, c = i % 768;
    float v;
    if (c < 256)      v = Wq[d * 256 + c];
    else if (c < 512) v = Wk[d * 256 + c - 256];
    else              v = Wv[d * 256 + c - 512];
    W[i] = v;
}

// ---------------------------------------------------------------------------
// Kernel 1: LayerNorm, one warp per 256-wide row. Block = 256 thr = 8 rows.
// ---------------------------------------------------------------------------
__global__ __launch_bounds__(256) void layernorm_kernel(
    const float* __restrict__ x, const float* __restrict__ gamma,
    const float* __restrict__ beta, float* __restrict__ out)
{
    int warp = threadIdx.x >> 5, lane = threadIdx.x & 31;
    size_t row = (size_t)blockIdx.x * 8 + warp;
    const float4* xr = (const float4*)(x + row * NEMBD);
    float4 a = xr[lane];
    float4 b = xr[lane + 32];
    float s  = a.x + a.y + a.z + a.w + b.x + b.y + b.z + b.w;
    float ss = a.x*a.x + a.y*a.y + a.z*a.z + a.w*a.w
             + b.x*b.x + b.y*b.y + b.z*b.z + b.w*b.w;
    #pragma unroll
    for (int o = 16; o > 0; o >>= 1) {
        s  += __shfl_xor_sync(0xFFFFFFFFu, s,  o);
        ss += __shfl_xor_sync(0xFFFFFFFFu, ss, o);
    }
    float mu  = s * (1.0f / 256.0f);
    float var = ss * (1.0f / 256.0f) - mu * mu;
    float rs  = rsqrtf(var + 1e-5f);
    float4 g0 = ((const float4*)gamma)[lane];
    float4 g1 = ((const float4*)gamma)[lane + 32];
    float4 be0 = ((const float4*)beta)[lane];
    float4 be1 = ((const float4*)beta)[lane + 32];
    float4 o0, o1;
    o0.x = (a.x - mu) * rs * g0.x + be0.x;
    o0.y = (a.y - mu) * rs * g0.y + be0.y;
    o0.z = (a.z - mu) * rs * g0.z + be0.z;
    o0.w = (a.w - mu) * rs * g0.w + be0.w;
    o1.x = (b.x - mu) * rs * g1.x + be1.x;
    o1.y = (b.y - mu) * rs * g1.y + be1.y;
    o1.z = (b.z - mu) * rs * g1.z + be1.z;
    o1.w = (b.w - mu) * rs * g1.w + be1.w;
    float4* orow = (float4*)(out + row * NEMBD);
    orow[lane]      = o0;
    orow[lane + 32] = o1;
}

// ---------------------------------------------------------------------------
// Kernel 2: tf32 tensor-core GEMM.  C[M,N] = A[M,K] @ B[K,N]  (+bias)(+relu)(+res)
// BM=128, BN=64, BK=32, 256 threads (8 warps: 4 along M x 2 along N, 32x32 each)
// ---------------------------------------------------------------------------
#define BM 128
#define BN 64
#define BK 32

template<bool HAS_BIAS, bool HAS_RES, bool DO_RELU>
__global__ __launch_bounds__(256) void gemm_tf32_kernel(
    const float* __restrict__ A, const float* __restrict__ B,
    float* __restrict__ C, const float* __restrict__ bias,
    const float* __restrict__ res, int N, int K)
{
    __shared__ uint32_t As[BM][BK + 4];   // stride 36 -> conflict-free frag reads
    __shared__ uint32_t Bs[BK][BN + 8];   // stride 72 -> conflict-free frag reads

    int tid  = threadIdx.x;
    int warp = tid >> 5, lane = tid & 31;
    int g = lane >> 2, tg = lane & 3;
    int wm = (warp & 3) * 32;   // warp row offset within block tile
    int wn = (warp >> 2) * 32;  // warp col offset within block tile
    int mBase = blockIdx.y * BM;
    int nBase = blockIdx.x * BN;

    float acc[2][4][4];
    #pragma unroll
    for (int mi = 0; mi < 2; mi++)
        #pragma unroll
        for (int ni = 0; ni < 4; ni++)
            #pragma unroll
            for (int i = 0; i < 4; i++) acc[mi][ni][i] = 0.0f;

    int aRow = tid >> 3;          // 0..31
    int aCol = (tid & 7) << 2;    // 0,4,...,28
    int bRow = tid >> 4;          // 0..15
    int bCol = (tid & 15) << 2;   // 0,4,...,60

    for (int k0 = 0; k0 < K; k0 += BK) {
        float4 av[4], bv[2];
        #pragma unroll
        for (int r = 0; r < 4; r++)
            av[r] = *(const float4*)&A[(size_t)(mBase + aRow + r * 32) * K + k0 + aCol];
        #pragma unroll
        for (int r = 0; r < 2; r++)
            bv[r] = *(const float4*)&B[(size_t)(k0 + bRow + r * 16) * N + nBase + bCol];

        __syncthreads();
        #pragma unroll
        for (int r = 0; r < 4; r++) {
            As[aRow + r * 32][aCol + 0] = f2tf(av[r].x);
            As[aRow + r * 32][aCol + 1] = f2tf(av[r].y);
            As[aRow + r * 32][aCol + 2] = f2tf(av[r].z);
            As[aRow + r * 32][aCol + 3] = f2tf(av[r].w);
        }
        #pragma unroll
        for (int r = 0; r < 2; r++) {
            Bs[bRow + r * 16][bCol + 0] = f2tf(bv[r].x);
            Bs[bRow + r * 16][bCol + 1] = f2tf(bv[r].y);
            Bs[bRow + r * 16][bCol + 2] = f2tf(bv[r].z);
            Bs[bRow + r * 16][bCol + 3] = f2tf(bv[r].w);
        }
        __syncthreads();

        #pragma unroll
        for (int kk = 0; kk < BK; kk += 8) {
            uint32_t af[2][4], bf[4][2];
            #pragma unroll
            for (int mi = 0; mi < 2; mi++) {
                int r0 = wm + mi * 16 + g;
                af[mi][0] = As[r0    ][kk + tg];
                af[mi][1] = As[r0 + 8][kk + tg];
                af[mi][2] = As[r0    ][kk + tg + 4];
                af[mi][3] = As[r0 + 8][kk + tg + 4];
            }
            #pragma unroll
            for (int ni = 0; ni < 4; ni++) {
                int c0 = wn + ni * 8 + g;
                bf[ni][0] = Bs[kk + tg    ][c0];
                bf[ni][1] = Bs[kk + tg + 4][c0];
            }
            #pragma unroll
            for (int mi = 0; mi < 2; mi++)
                #pragma unroll
                for (int ni = 0; ni < 4; ni++)
                    mma_tf32(acc[mi][ni], af[mi], bf[ni]);
        }
    }

    // Epilogue
    #pragma unroll
    for (int mi = 0; mi < 2; mi++) {
        #pragma unroll
        for (int ni = 0; ni < 4; ni++) {
            int col = nBase + wn + ni * 8 + tg * 2;
            #pragma unroll
            for (int hh = 0; hh < 2; hh++) {
                int row = mBase + wm + mi * 16 + g + hh * 8;
                float v0 = acc[mi][ni][2 * hh];
                float v1 = acc[mi][ni][2 * hh + 1];
                if (HAS_BIAS) { v0 += bias[col]; v1 += bias[col + 1]; }
                if (DO_RELU)  { v0 = fmaxf(v0, 0.0f); v1 = fmaxf(v1, 0.0f); }
                if (HAS_RES) {
                    v0 += res[(size_t)row * N + col];
                    v1 += res[(size_t)row * N + col + 1];
                }
                *(float2*)&C[(size_t)row * N + col] = make_float2(v0, v1);
            }
        }
    }
}

// ---------------------------------------------------------------------------
// Kernel 3: causal attention, one block per (b,h). Thread t = query row t.
// K/V staged in 2 tiles of 128 keys (32KB static smem); online softmax;
// packed f32x2 math. No dynamic smem, no attribute opt-in required.
// ---------------------------------------------------------------------------
#define STILE 128

__global__ __launch_bounds__(256) void attention_kernel(
    const float* __restrict__ qkv, float* __restrict__ attn)
{
    __shared__ float Ks[STILE * 32];   // 16 KB
    __shared__ float Vs[STILE * 32];   // 16 KB

    int bh = blockIdx.x;
    int b = bh >> 3, h = bh & 7;
    const float* base = qkv + (size_t)b * SEQ * 768 + h * HEADSZ;

    int t = threadIdx.x;
    u64 q2[16];
    const u64* qp = (const u64*)(base + (size_t)t * 768);
    #pragma unroll
    for (int i = 0; i < 16; i++) q2[i] = qp[i];

    u64 acc2[16];
    #pragma unroll
    for (int i = 0; i < 16; i++) acc2[i] = 0ull;
    float m = -1e30f, l = 0.0f;
    const float scale = 0.17677669529663687f;   // 1/sqrt(32)

    for (int tile = 0; tile < SEQ; tile += STILE) {
        // Stage this tile of K and V (128 rows x 8 float4 = 1024 f4; 4/thread).
        __syncthreads();
        for (int idx = t; idx < STILE * 8; idx += 256) {
            int row = idx >> 3, c4 = (idx & 7) << 2;
            ((float4*)Ks)[idx] = *(const float4*)&base[(size_t)(tile + row) * 768 + 256 + c4];
            ((float4*)Vs)[idx] = *(const float4*)&base[(size_t)(tile + row) * 768 + 512 + c4];
        }
        __syncthreads();

        if (t < tile) continue;                 // fully masked tile for this query
        int smax = t - tile;                    // last valid local key index
        if (smax > STILE - 1) smax = STILE - 1;

        for (int s0 = 0; s0 <= smax; s0 += 32) {
            float sc[32];
            float tmax = -1e30f;
            #pragma unroll
            for (int j = 0; j < 32; j++) {
                int s = s0 + j;
                int sr = s <= smax ? s : 0;     // clamp masked lanes in-bounds
                const u64* kr = (const u64*)(Ks + sr * 32);
                u64 d2 = 0ull;
                #pragma unroll
                for (int i = 0; i < 16; i++) d2 = ffma2(q2[i], kr[i], d2);
                float2 dv = unpack2(d2);
                float d = (dv.x + dv.y) * scale;
                sc[j] = (s <= smax) ? d : -1e30f;
                tmax = fmaxf(tmax, sc[j]);
            }
            float nm = fmaxf(m, tmax);
            float corr = __expf(m - nm);
            l *= corr;
            u64 c2 = pack2(corr, corr);
            #pragma unroll
            for (int i = 0; i < 16; i++) acc2[i] = fmul2(acc2[i], c2);
            #pragma unroll
            for (int j = 0; j < 32; j++) {
                int s = s0 + j; if (s > smax) s = 0;
                float p = __expf(sc[j] - nm);   // masked -> exp(-1e30) = 0
                l += p;
                u64 p2 = pack2(p, p);
                const u64* vr = (const u64*)(Vs + s * 32);
                #pragma unroll
                for (int i = 0; i < 16; i++) acc2[i] = ffma2(p2, vr[i], acc2[i]);
            }
            m = nm;
        }
    }

    float inv = 1.0f / l;
    float2* outp = (float2*)(attn + ((size_t)b * SEQ + t) * NEMBD + h * HEADSZ);
    #pragma unroll
    for (int i = 0; i < 16; i++) {
        float2 a = unpack2(acc2[i]);
        outp[i] = make_float2(a.x * inv, a.y * inv);
    }
}

// ---------------------------------------------------------------------------
// Launch
// ---------------------------------------------------------------------------
extern "C" void kernel_launch(void* const* d_in, const int* in_sizes, int n_in,
                              void* d_out, int out_size)
{
    const float* x    = (const float*)d_in[0];
    const float* Wq   = (const float*)d_in[1];
    const float* Wk   = (const float*)d_in[2];
    const float* Wv   = (const float*)d_in[3];
    const float* Wo   = (const float*)d_in[4];
    const float* bo   = (const float*)d_in[5];
    const float* ln1g = (const float*)d_in[6];
    const float* ln1b = (const float*)d_in[7];
    const float* ln2g = (const float*)d_in[8];
    const float* ln2b = (const float*)d_in[9];
    const float* W1   = (const float*)d_in[10];
    const float* b1   = (const float*)d_in[11];
    const float* W2   = (const float*)d_in[12];
    const float* b2   = (const float*)d_in[13];
    float* out = (float*)d_out;

    float *ph, *pqkv, *pattn, *px1, *pffh, *pwqkv;
    cudaGetSymbolAddress((void**)&ph,    g_h);
    cudaGetSymbolAddress((void**)&pqkv,  g_qkv);
    cudaGetSymbolAddress((void**)&pattn, g_attn);
    cudaGetSymbolAddress((void**)&px1,   g_x1);
    cudaGetSymbolAddress((void**)&pffh,  g_ffh);
    cudaGetSymbolAddress((void**)&pwqkv, g_wqkv);

    // 0) concat qkv weights
    concat_w_kernel<<<768, 256>>>(Wq, Wk, Wv, pwqkv);

    // 1) LN1: x -> h
    layernorm_kernel<<<M_TOT / 8, 256>>>(x, ln1g, ln1b, ph);

    // 2) fused QKV GEMM: h[65536,256] @ Wqkv[256,768] -> qkv
    gemm_tf32_kernel<false, false, false><<<dim3(768 / BN, M_TOT / BM), 256>>>(
        ph, pwqkv, pqkv, nullptr, nullptr, 768, 256);

    // 3) attention: qkv -> attn
    attention_kernel<<<BATCH * NHEADS, 256>>>(pqkv, pattn);

    // 4) O projection + bias + residual: x1 = x + attn @ Wo + bo
    gemm_tf32_kernel<true, true, false><<<dim3(NEMBD / BN, M_TOT / BM), 256>>>(
        pattn, Wo, px1, bo, x, NEMBD, 256);

    // 5) LN2: x1 -> h
    layernorm_kernel<<<M_TOT / 8, 256>>>(px1, ln2g, ln2b, ph);

    // 6) FFN up + relu: ffh = relu(h @ W1 + b1)
    gemm_tf32_kernel<true, false, true><<<dim3(FFDIM / BN, M_TOT / BM), 256>>>(
        ph, W1, pffh, b1, nullptr, FFDIM, 256);

    // 7) FFN down + bias + residual: out = x1 + ffh @ W2 + b2
    gemm_tf32_kernel<true, true, false><<<dim3(NEMBD / BN, M_TOT / BM), 256>>>(
        pffh, W2, out, b2, px1, NEMBD, FFDIM);
}